// round 12
// baseline (speedup 1.0000x reference)
#include <cuda_runtime.h>
#include <math.h>
#include <stdint.h>

#define BSZ   16
#define SLEN  256
#define TDEC  99
#define EDIM  768
#define HDIM  512
#define H3    1536
#define H2    1024
#define VOC   30522
#define MDEC  (TDEC*BSZ)

// ---------------- device scratch ----------------
__device__ float g_gi_f[SLEN*BSZ*H3];
__device__ float g_gi_b[SLEN*BSZ*H3];
__device__ float g_enc_out[SLEN*BSZ*H2];
__device__ float g_gidec[MDEC*H3];
__device__ float g_hall[MDEC*HDIM];
__device__ float g_h_enc[4*BSZ*HDIM];     // [dir*2+parity][b][k]
__device__ float g_hd[2*BSZ*HDIM];        // [parity][b][k]
__device__ float g_hfinal[2*BSZ*HDIM];    // [dir][b][k]
__device__ float g_v[H2];
__device__ float g_ctxraw[BSZ*H2];
__device__ float g_ctx[BSZ*HDIM];
__device__ float g_cdec[BSZ*H3];
__device__ float g_ctxbias[(size_t)BSZ*VOC];
__device__ int   g_rowidx[MDEC];
__device__ unsigned g_bar[2];

__global__ void k_init(const int* __restrict__ ids) {
    int i = blockIdx.x * blockDim.x + threadIdx.x;
    if (i < 2) g_bar[i] = 0u;
    if (i < 4*BSZ*HDIM) g_h_enc[i] = 0.f;
    if (i < MDEC) {
        int b = i & 15, t = i >> 4;
        g_rowidx[i] = ids[b * 100 + t];
    }
}

__device__ __forceinline__ void grid_barrier(unsigned* ctr, unsigned target) {
    __syncthreads();
    if (threadIdx.x == 0) {
        __threadfence();
        atomicAdd(ctr, 1u);
        while (*((volatile unsigned*)ctr) < target) __nanosleep(64);
        __threadfence();
    }
    __syncthreads();
}

// C[m][n] = sum_k A[m][k]*B[n][k] + bias ; tile 128x128x16
// MODE 0: C row -> (m&255)*16+(m>>8)      (enc gates, [s][b])
// MODE 1: A row gathered via g_rowidx[m]  (dec emb gates)
// MODE 2: bias = ctxbias[(m&15)*N+n], C row -> (m&15)*TDEC+(m>>4)
template<int MODE>
__global__ __launch_bounds__(256) void k_gemm(
    const float* __restrict__ A, const float* __restrict__ Bm,
    const float* __restrict__ bias, float* __restrict__ C,
    int M, int N, int K, int lda, int ldb)
{
    __shared__ float As[16][132];
    __shared__ float Bs[16][132];
    const int tid = threadIdx.x;
    const int m0 = blockIdx.y * 128, n0 = blockIdx.x * 128;

    const float* aptr[2]; const float* bptr[2];
    int rr[2], kq[2];
#pragma unroll
    for (int i = 0; i < 2; i++) {
        int c = tid + 256 * i;
        rr[i] = c & 127; kq[i] = c >> 7;
        int mr = m0 + rr[i]; if (mr >= M) mr = 0;
        if (MODE == 1) mr = g_rowidx[mr];
        aptr[i] = A + (size_t)mr * lda + kq[i] * 4;
        int nr = n0 + rr[i]; if (nr >= N) nr = 0;
        bptr[i] = Bm + (size_t)nr * ldb + kq[i] * 4;
    }

    const int tm = (tid & 15) * 8, tn = (tid >> 4) * 8;
    float acc[8][8];
#pragma unroll
    for (int i = 0; i < 8; i++)
#pragma unroll
        for (int j = 0; j < 8; j++) acc[i][j] = 0.f;

    float4 ra[2], rb[2];
#pragma unroll
    for (int i = 0; i < 2; i++) { ra[i] = *(const float4*)aptr[i]; rb[i] = *(const float4*)bptr[i]; }

    for (int kt = 0; ; ) {
        __syncthreads();
#pragma unroll
        for (int i = 0; i < 2; i++) {
            int kk = kq[i] * 4, r = rr[i];
            As[kk+0][r]=ra[i].x; As[kk+1][r]=ra[i].y; As[kk+2][r]=ra[i].z; As[kk+3][r]=ra[i].w;
            Bs[kk+0][r]=rb[i].x; Bs[kk+1][r]=rb[i].y; Bs[kk+2][r]=rb[i].z; Bs[kk+3][r]=rb[i].w;
        }
        __syncthreads();
        bool more = (kt + 16 < K);
        if (more) {
#pragma unroll
            for (int i = 0; i < 2; i++) {
                aptr[i] += 16; bptr[i] += 16;
                ra[i] = *(const float4*)aptr[i]; rb[i] = *(const float4*)bptr[i];
            }
        }
#pragma unroll
        for (int k = 0; k < 16; k++) {
            float4 a0 = *(const float4*)&As[k][tm], a1 = *(const float4*)&As[k][tm+4];
            float4 b0 = *(const float4*)&Bs[k][tn], b1 = *(const float4*)&Bs[k][tn+4];
            float av[8] = {a0.x,a0.y,a0.z,a0.w,a1.x,a1.y,a1.z,a1.w};
            float bv[8] = {b0.x,b0.y,b0.z,b0.w,b1.x,b1.y,b1.z,b1.w};
#pragma unroll
            for (int i = 0; i < 8; i++)
#pragma unroll
                for (int j = 0; j < 8; j++) acc[i][j] += av[i] * bv[j];
        }
        kt += 16;
        if (!more) break;
    }

#pragma unroll
    for (int i = 0; i < 8; i++) {
        int m = m0 + tm + i;
        if (m >= M) continue;
        size_t crow;
        if (MODE == 0)      crow = (size_t)((m & 255) * 16 + (m >> 8)) * (size_t)N;
        else if (MODE == 1) crow = (size_t)m * (size_t)N;
        else                crow = (size_t)((m & 15) * TDEC + (m >> 4)) * (size_t)N;
#pragma unroll
        for (int j = 0; j < 8; j++) {
            int n = n0 + tn + j;
            if (n < N) {
                float vb = (MODE == 2) ? bias[(size_t)(m & 15) * (size_t)N + n] : bias[n];
                C[crow + n] = acc[i][j] + vb;
            }
        }
    }
}

// encoder scan: 128 CTAs = 2 dirs x 64 slices of 8 h-dims, 384 threads
__global__ __launch_bounds__(384) void k_enc_scan(
    const float* __restrict__ Whh_f, const float* __restrict__ Whh_b,
    const float* __restrict__ bhh_f, const float* __restrict__ bhh_b)
{
    __shared__ float sH[16 * 516];
    __shared__ float sGh[24 * 16];
    __shared__ float sB[24];
    const int bx = blockIdx.x, dir = bx >> 6, jh0 = (bx & 63) * 8, tid = threadIdx.x;
    const float* Whh = dir ? Whh_b : Whh_f;
    const float* gi_base = dir ? g_gi_b : g_gi_f;
    if (tid < 24) sB[tid] = (dir ? bhh_b : bhh_f)[(tid >> 3) * HDIM + jh0 + (tid & 7)];

    const int jl = tid >> 4, bb = tid & 15;
    const float* wptr = Whh + (size_t)((jl >> 3) * HDIM + jh0 + (jl & 7)) * HDIM;

    for (int s = 0; s < SLEN; s++) {
        int par = s & 1;
        const float* hg = g_h_enc + (size_t)(dir * 2 + par) * BSZ * HDIM;
        for (int idx = tid * 4; idx < BSZ * HDIM; idx += 384 * 4) {
            int b = idx >> 9, k = idx & 511;
            *(float4*)(sH + b * 516 + k) = *(const float4*)(hg + b * HDIM + k);
        }
        __syncthreads();
        const float* hrow = sH + bb * 516;
        float a0=0.f,a1=0.f,a2=0.f,a3=0.f;
#pragma unroll 8
        for (int k = 0; k < HDIM; k += 4) {
            float4 w = __ldg((const float4*)(wptr + k));
            float4 h = *(const float4*)(hrow + k);
            a0 += w.x*h.x; a1 += w.y*h.y; a2 += w.z*h.z; a3 += w.w*h.w;
        }
        sGh[jl * 16 + bb] = (a0+a1)+(a2+a3) + sB[jl];
        __syncthreads();

        int s_x = dir ? (SLEN - 1 - s) : s;
        if (tid < 128) {
            int b = tid >> 3, lh = tid & 7;
            const float* gi = gi_base + (size_t)(s_x * BSZ + b) * H3 + jh0 + lh;
            float gir = gi[0], giz = gi[HDIM], gin = gi[2*HDIM];
            float ghr = sGh[lh*16+b], ghz = sGh[(8+lh)*16+b], ghn = sGh[(16+lh)*16+b];
            float hold = sH[b * 516 + jh0 + lh];
            float r = 1.f / (1.f + expf(-(gir + ghr)));
            float z = 1.f / (1.f + expf(-(giz + ghz)));
            float n = tanhf(gin + r * ghn);
            float hnew = (1.f - z) * n + z * hold;
            g_h_enc[((dir*2 + (par^1)) * BSZ + b) * HDIM + jh0 + lh] = hnew;
            g_enc_out[(size_t)(s_x * BSZ + b) * H2 + dir * HDIM + jh0 + lh] = hnew;
            if (s == SLEN - 1) g_hfinal[(dir * BSZ + b) * HDIM + jh0 + lh] = hnew;
        }
        grid_barrier(&g_bar[0], 128u * (unsigned)(s + 1));
    }
}

// decoder scan: 64 CTAs x slices of 8, 384 threads
__global__ __launch_bounds__(384) void k_dec_scan(
    const float* __restrict__ Whh, const float* __restrict__ bhh)
{
    __shared__ float sH[16 * 516];
    __shared__ float sGh[24 * 16];
    __shared__ float sB[24];
    const int jh0 = blockIdx.x * 8, tid = threadIdx.x;
    if (tid < 24) sB[tid] = bhh[(tid >> 3) * HDIM + jh0 + (tid & 7)];
    const int jl = tid >> 4, bb = tid & 15;
    const float* wptr = Whh + (size_t)((jl >> 3) * HDIM + jh0 + (jl & 7)) * HDIM;

    for (int t = 0; t < TDEC; t++) {
        int par = t & 1;
        const float* hg = g_hd + (size_t)par * BSZ * HDIM;
        for (int idx = tid * 4; idx < BSZ * HDIM; idx += 384 * 4) {
            int b = idx >> 9, k = idx & 511;
            *(float4*)(sH + b * 516 + k) = *(const float4*)(hg + b * HDIM + k);
        }
        __syncthreads();
        const float* hrow = sH + bb * 516;
        float a0=0.f,a1=0.f,a2=0.f,a3=0.f;
#pragma unroll 8
        for (int k = 0; k < HDIM; k += 4) {
            float4 w = __ldg((const float4*)(wptr + k));
            float4 h = *(const float4*)(hrow + k);
            a0 += w.x*h.x; a1 += w.y*h.y; a2 += w.z*h.z; a3 += w.w*h.w;
        }
        sGh[jl * 16 + bb] = (a0+a1)+(a2+a3) + sB[jl];
        __syncthreads();

        if (tid < 128) {
            int b = tid >> 3, lh = tid & 7;
            size_t gio = (size_t)(t * BSZ + b) * H3 + jh0 + lh;
            size_t cdo = (size_t)b * H3 + jh0 + lh;
            float gir = g_gidec[gio]          + g_cdec[cdo];
            float giz = g_gidec[gio + HDIM]   + g_cdec[cdo + HDIM];
            float gin = g_gidec[gio + 2*HDIM] + g_cdec[cdo + 2*HDIM];
            float ghr = sGh[lh*16+b], ghz = sGh[(8+lh)*16+b], ghn = sGh[(16+lh)*16+b];
            float hold = sH[b * 516 + jh0 + lh];
            float r = 1.f / (1.f + expf(-(gir + ghr)));
            float z = 1.f / (1.f + expf(-(giz + ghz)));
            float n = tanhf(gin + r * ghn);
            float hnew = (1.f - z) * n + z * hold;
            g_hd[((par^1) * BSZ + b) * HDIM + jh0 + lh] = hnew;
            g_hall[(size_t)(t * BSZ + b) * HDIM + jh0 + lh] = hnew;
        }
        grid_barrier(&g_bar[1], 64u * (unsigned)(t + 1));
    }
}

__global__ void k_v2h(const float* __restrict__ attn_W, const float* __restrict__ comb_W) {
    __shared__ float sc[HDIM];
    int tid = threadIdx.x;
    sc[tid] = comb_W[tid];
    __syncthreads();
    int c = blockIdx.x * 512 + tid;
    float acc = 0.f;
    for (int i = 0; i < HDIM; i++) acc += sc[i] * attn_W[(size_t)i * H3 + c];
    g_v[c] = acc;
}

__global__ __launch_bounds__(256) void k_attention(const int* __restrict__ mask) {
    __shared__ float sv[H2];
    __shared__ float sw[SLEN];
    __shared__ float red[SLEN];
    int b = blockIdx.x, tid = threadIdx.x;
    for (int i = tid; i < H2; i += 256) sv[i] = g_v[i];
    __syncthreads();
    float score = -1e30f;
    if (mask[b * SLEN + tid] > 0) {
        const float* e = g_enc_out + (size_t)(tid * BSZ + b) * H2;
        float a0=0.f,a1=0.f,a2=0.f,a3=0.f;
        for (int d = 0; d < H2; d += 4) {
            float4 ev = *(const float4*)(e + d);
            a0 += sv[d]*ev.x; a1 += sv[d+1]*ev.y; a2 += sv[d+2]*ev.z; a3 += sv[d+3]*ev.w;
        }
        score = (a0+a1)+(a2+a3);
    }
    red[tid] = score; __syncthreads();
    for (int o = 128; o; o >>= 1) { if (tid < o) red[tid] = fmaxf(red[tid], red[tid+o]); __syncthreads(); }
    float mx = red[0]; __syncthreads();
    float ex = (score > -1e29f) ? expf(score - mx) : 0.f;
    red[tid] = ex; __syncthreads();
    for (int o = 128; o; o >>= 1) { if (tid < o) red[tid] += red[tid+o]; __syncthreads(); }
    sw[tid] = ex / red[0];
    __syncthreads();
    float4 acc = make_float4(0.f,0.f,0.f,0.f);
    const float* base = g_enc_out + b * H2 + tid * 4;
    for (int s = 0; s < SLEN; s++) {
        float w = sw[s];
        float4 ev = *(const float4*)(base + (size_t)s * BSZ * H2);
        acc.x += w*ev.x; acc.y += w*ev.y; acc.z += w*ev.z; acc.w += w*ev.w;
    }
    *(float4*)(g_ctxraw + b * H2 + tid * 4) = acc;
}

__global__ void k_ctx_proj(const float* __restrict__ proj_W, const float* __restrict__ proj_b) {
    __shared__ float sc[H2];
    int b = blockIdx.x, j = threadIdx.x;
    for (int i = j; i < H2; i += 512) sc[i] = g_ctxraw[b * H2 + i];
    __syncthreads();
    const float* w = proj_W + (size_t)j * H2;
    float a0=0.f,a1=0.f,a2=0.f,a3=0.f;
    for (int d = 0; d < H2; d += 4) {
        float4 wv = *(const float4*)(w + d);
        a0 += sc[d]*wv.x; a1 += sc[d+1]*wv.y; a2 += sc[d+2]*wv.z; a3 += sc[d+3]*wv.w;
    }
    g_ctx[b * HDIM + j] = proj_b[j] + (a0+a1)+(a2+a3);
}

__global__ void k_cdec(const float* __restrict__ dec_Wih) {
    __shared__ float sc[HDIM];
    int b = blockIdx.x, tid = threadIdx.x;
    sc[tid] = g_ctx[b * HDIM + tid];
    __syncthreads();
    for (int r = 0; r < 3; r++) {
        int j3 = r * HDIM + tid;
        const float* w = dec_Wih + (size_t)j3 * (EDIM + HDIM) + EDIM;
        float a0=0.f,a1=0.f,a2=0.f,a3=0.f;
        for (int d = 0; d < HDIM; d += 4) {
            float4 wv = *(const float4*)(w + d);
            a0 += sc[d]*wv.x; a1 += sc[d+1]*wv.y; a2 += sc[d+2]*wv.z; a3 += sc[d+3]*wv.w;
        }
        g_cdec[b * H3 + j3] = (a0+a1)+(a2+a3);
    }
}

__global__ void k_hinit() {
    int b = blockIdx.x, k = threadIdx.x;
    g_hd[b * HDIM + k] = g_hfinal[b * HDIM + k] + g_hfinal[(BSZ + b) * HDIM + k];
}

__global__ __launch_bounds__(128) void k_ctxbias(const float* __restrict__ out_W,
                                                 const float* __restrict__ out_b) {
    __shared__ float sc[BSZ * HDIM];
    int tid = threadIdx.x;
    for (int i = tid; i < BSZ * HDIM; i += 128) sc[i] = g_ctx[i];
    __syncthreads();
    int v = blockIdx.x * 128 + tid;
    if (v >= VOC) return;
    float acc[BSZ];
#pragma unroll
    for (int b = 0; b < BSZ; b++) acc[b] = 0.f;
    const float* w = out_W + (size_t)v * H2 + HDIM;
    for (int d = 0; d < HDIM; d += 4) {
        float4 wv = *(const float4*)(w + d);
#pragma unroll
        for (int b = 0; b < BSZ; b++) {
            const float* cb = sc + b * HDIM + d;
            acc[b] += cb[0]*wv.x + cb[1]*wv.y + cb[2]*wv.z + cb[3]*wv.w;
        }
    }
    float ob = out_b[v];
#pragma unroll
    for (int b = 0; b < BSZ; b++) g_ctxbias[(size_t)b * VOC + v] = acc[b] + ob;
}

extern "C" void kernel_launch(void* const* d_in, const int* in_sizes, int n_in,
                              void* d_out, int out_size) {
    const float* bert    = (const float*)d_in[0];
    const int*   mask    = (const int*)  d_in[1];
    const int*   ids     = (const int*)  d_in[2];
    const float* emb     = (const float*)d_in[3];
    const float* eWih_f  = (const float*)d_in[4];
    const float* eWhh_f  = (const float*)d_in[5];
    const float* ebih_f  = (const float*)d_in[6];
    const float* ebhh_f  = (const float*)d_in[7];
    const float* eWih_b  = (const float*)d_in[8];
    const float* eWhh_b  = (const float*)d_in[9];
    const float* ebih_b  = (const float*)d_in[10];
    const float* ebhh_b  = (const float*)d_in[11];
    const float* dWih    = (const float*)d_in[12];
    const float* dWhh    = (const float*)d_in[13];
    const float* dbih    = (const float*)d_in[14];
    const float* dbhh    = (const float*)d_in[15];
    const float* attn_W  = (const float*)d_in[16];
    const float* proj_W  = (const float*)d_in[20];
    const float* proj_b  = (const float*)d_in[21];
    const float* out_W   = (const float*)d_in[22];
    const float* out_b   = (const float*)d_in[23];
    const float* comb_W  = (const float*)d_in[18];
    float* out = (float*)d_out;

    float *gi_f, *gi_b, *gidec, *hall, *ctxbias;
    cudaGetSymbolAddress((void**)&gi_f,   g_gi_f);
    cudaGetSymbolAddress((void**)&gi_b,   g_gi_b);
    cudaGetSymbolAddress((void**)&gidec,  g_gidec);
    cudaGetSymbolAddress((void**)&hall,   g_hall);
    cudaGetSymbolAddress((void**)&ctxbias,g_ctxbias);

    k_init<<<128, 256>>>(ids);

    // encoder input gates: [4096,768] x [1536,768]^T
    k_gemm<0><<<dim3(12, 32), 256>>>(bert, eWih_f, ebih_f, gi_f, SLEN*BSZ, H3, EDIM, EDIM, EDIM);
    k_gemm<0><<<dim3(12, 32), 256>>>(bert, eWih_b, ebih_b, gi_b, SLEN*BSZ, H3, EDIM, EDIM, EDIM);
    // decoder embedding gates (gathered rows): [1584,768] x [1536,1280(first 768)]^T
    k_gemm<1><<<dim3(12, 13), 256>>>(emb, dWih, dbih, gidec, MDEC, H3, EDIM, EDIM, EDIM + HDIM);
    // v = comb_W @ attn_W[:, :2H]
    k_v2h<<<2, 512>>>(attn_W, comb_W);

    // encoder bidirectional scan (persistent, 128 CTAs)
    k_enc_scan<<<128, 384>>>(eWhh_f, eWhh_b, ebhh_f, ebhh_b);

    // step-invariant attention + context
    k_attention<<<BSZ, 256>>>(mask);
    k_ctx_proj<<<BSZ, 512>>>(proj_W, proj_b);
    k_cdec<<<BSZ, 512>>>(dWih);
    k_ctxbias<<<(VOC + 127) / 128, 128>>>(out_W, out_b);
    k_hinit<<<BSZ, 512>>>();

    // decoder scan (persistent, 64 CTAs)
    k_dec_scan<<<64, 384>>>(dWhh, dbhh);

    // logits: [1584,512] x [30522,1024(first 512)]^T + ctxbias -> out[b][t][v]
    k_gemm<2><<<dim3(239, 13), 256>>>(hall, out_W, ctxbias, out, MDEC, VOC, HDIM, HDIM, H2);
}

// round 13
// speedup vs baseline: 1.1420x; 1.1420x over previous
#include <cuda_runtime.h>
#include <math.h>
#include <stdint.h>

#define BSZ   16
#define SLEN  256
#define TDEC  99
#define EDIM  768
#define HDIM  512
#define H3    1536
#define H2    1024
#define VOC   30522
#define MDEC  (TDEC*BSZ)

// ---------------- device scratch ----------------
__device__ float g_gi_f[SLEN*BSZ*H3];
__device__ float g_gi_b[SLEN*BSZ*H3];
__device__ float g_enc_out[SLEN*BSZ*H2];
__device__ float g_gidec[MDEC*H3];
__device__ float g_hall[MDEC*HDIM];
__device__ float g_h_enc[4*BSZ*HDIM];     // [dir*2+parity][b][k]
__device__ float g_hd[2*BSZ*HDIM];        // [parity][b][k]
__device__ float g_hfinal[2*BSZ*HDIM];    // [dir][b][k]
__device__ float g_v[H2];
__device__ float g_ctxraw[BSZ*H2];
__device__ float g_ctx[BSZ*HDIM];
__device__ float g_cdec[BSZ*H3];
__device__ float g_ctxbias[(size_t)BSZ*VOC];
__device__ int   g_rowidx[MDEC];
__device__ unsigned g_bar[2];

__global__ void k_init(const int* __restrict__ ids) {
    int i = blockIdx.x * blockDim.x + threadIdx.x;
    if (i < 2) g_bar[i] = 0u;
    if (i < 4*BSZ*HDIM) g_h_enc[i] = 0.f;
    if (i < MDEC) {
        int b = i & 15, t = i >> 4;
        g_rowidx[i] = ids[b * 100 + t];
    }
}

__device__ __forceinline__ void grid_barrier(unsigned* ctr, unsigned target) {
    __syncthreads();
    if (threadIdx.x == 0) {
        __threadfence();
        atomicAdd(ctr, 1u);
        while (*((volatile unsigned*)ctr) < target) __nanosleep(64);
        __threadfence();
    }
    __syncthreads();
}

// ---------------- fp32 SGEMM (gates): C[m][n]=sum_k A[m][k]B[n][k]+bias ----
// MODE 0: C row -> (m&255)*16+(m>>8)      (enc gates, [s][b])
// MODE 1: A row gathered via g_rowidx[m]  (dec emb gates)
template<int MODE>
__global__ __launch_bounds__(256) void k_gemm(
    const float* __restrict__ A, const float* __restrict__ Bm,
    const float* __restrict__ bias, float* __restrict__ C,
    int M, int N, int K, int lda, int ldb)
{
    __shared__ float As[16][132];
    __shared__ float Bs[16][132];
    const int tid = threadIdx.x;
    const int m0 = blockIdx.y * 128, n0 = blockIdx.x * 128;

    const float* aptr[2]; const float* bptr[2];
    int rr[2], kq[2];
#pragma unroll
    for (int i = 0; i < 2; i++) {
        int c = tid + 256 * i;
        rr[i] = c & 127; kq[i] = c >> 7;
        int mr = m0 + rr[i]; if (mr >= M) mr = 0;
        if (MODE == 1) mr = g_rowidx[mr];
        aptr[i] = A + (size_t)mr * lda + kq[i] * 4;
        int nr = n0 + rr[i]; if (nr >= N) nr = 0;
        bptr[i] = Bm + (size_t)nr * ldb + kq[i] * 4;
    }

    const int tm = (tid & 15) * 8, tn = (tid >> 4) * 8;
    float acc[8][8];
#pragma unroll
    for (int i = 0; i < 8; i++)
#pragma unroll
        for (int j = 0; j < 8; j++) acc[i][j] = 0.f;

    float4 ra[2], rb[2];
#pragma unroll
    for (int i = 0; i < 2; i++) { ra[i] = *(const float4*)aptr[i]; rb[i] = *(const float4*)bptr[i]; }

    for (int kt = 0; ; ) {
        __syncthreads();
#pragma unroll
        for (int i = 0; i < 2; i++) {
            int kk = kq[i] * 4, r = rr[i];
            As[kk+0][r]=ra[i].x; As[kk+1][r]=ra[i].y; As[kk+2][r]=ra[i].z; As[kk+3][r]=ra[i].w;
            Bs[kk+0][r]=rb[i].x; Bs[kk+1][r]=rb[i].y; Bs[kk+2][r]=rb[i].z; Bs[kk+3][r]=rb[i].w;
        }
        __syncthreads();
        bool more = (kt + 16 < K);
        if (more) {
#pragma unroll
            for (int i = 0; i < 2; i++) {
                aptr[i] += 16; bptr[i] += 16;
                ra[i] = *(const float4*)aptr[i]; rb[i] = *(const float4*)bptr[i];
            }
        }
#pragma unroll
        for (int k = 0; k < 16; k++) {
            float4 a0 = *(const float4*)&As[k][tm], a1 = *(const float4*)&As[k][tm+4];
            float4 b0 = *(const float4*)&Bs[k][tn], b1 = *(const float4*)&Bs[k][tn+4];
            float av[8] = {a0.x,a0.y,a0.z,a0.w,a1.x,a1.y,a1.z,a1.w};
            float bv[8] = {b0.x,b0.y,b0.z,b0.w,b1.x,b1.y,b1.z,b1.w};
#pragma unroll
            for (int i = 0; i < 8; i++)
#pragma unroll
                for (int j = 0; j < 8; j++) acc[i][j] += av[i] * bv[j];
        }
        kt += 16;
        if (!more) break;
    }

#pragma unroll
    for (int i = 0; i < 8; i++) {
        int m = m0 + tm + i;
        if (m >= M) continue;
        size_t crow;
        if (MODE == 0)      crow = (size_t)((m & 255) * 16 + (m >> 8)) * (size_t)N;
        else                crow = (size_t)m * (size_t)N;
#pragma unroll
        for (int j = 0; j < 8; j++) {
            int n = n0 + tn + j;
            if (n < N) C[crow + n] = acc[i][j] + bias[n];
        }
    }
}

// ---------------- tf32 tensor-core GEMM for the logits ---------------------
// C' = hall[1584,512] x out_W[:, :512]^T (ldb=1024) ; bias=ctxbias[(m&15)*VOC+n]
// output row (m&15)*TDEC + (m>>4)  ->  out[b][t][v]
__device__ __forceinline__ uint32_t f2tf32(float x) {
    uint32_t u;
    asm("cvt.rna.tf32.f32 %0, %1;" : "=r"(u) : "f"(x));
    return u;
}
__device__ __forceinline__ void mma_tf32(float c[4], const uint32_t a[4], const uint32_t b[2]) {
    asm volatile(
        "mma.sync.aligned.m16n8k8.row.col.f32.tf32.tf32.f32 "
        "{%0,%1,%2,%3}, {%4,%5,%6,%7}, {%8,%9}, {%0,%1,%2,%3};"
        : "+f"(c[0]), "+f"(c[1]), "+f"(c[2]), "+f"(c[3])
        : "r"(a[0]), "r"(a[1]), "r"(a[2]), "r"(a[3]), "r"(b[0]), "r"(b[1]));
}

__global__ __launch_bounds__(256) void k_gemm_out_tf32(
    const float* __restrict__ A, const float* __restrict__ Bm,
    const float* __restrict__ bias, float* __restrict__ C)
{
    __shared__ uint32_t As[2][16][132];   // [buf][k][m]
    __shared__ uint32_t Bs[2][16][132];   // [buf][k][n]
    const int tid = threadIdx.x;
    const int m0 = blockIdx.y * 128, n0 = blockIdx.x * 128;
    const int w = tid >> 5, lane = tid & 31;
    const int g = lane >> 2, cc = lane & 3;
    const int wm = (w & 1) * 64, wn = (w >> 1) * 32;

    // global load mapping: 512 float4 chunks per matrix, 2 per thread
    const float* aptr[2]; const float* bptr[2];
    int rr[2], kq[2];
#pragma unroll
    for (int i = 0; i < 2; i++) {
        int cidx = tid + 256 * i;
        rr[i] = cidx >> 2;          // 0..127 tile row
        kq[i] = cidx & 3;           // which float4 within k16
        int mr = m0 + rr[i]; if (mr >= MDEC) mr = 0;
        aptr[i] = A + (size_t)mr * HDIM + kq[i] * 4;
        int nr = n0 + rr[i]; if (nr >= VOC) nr = 0;
        bptr[i] = Bm + (size_t)nr * H2 + kq[i] * 4;
    }

    float acc[4][4][4];
#pragma unroll
    for (int mt = 0; mt < 4; mt++)
#pragma unroll
        for (int nt = 0; nt < 4; nt++)
#pragma unroll
            for (int q = 0; q < 4; q++) acc[mt][nt][q] = 0.f;

    float4 ra[2], rb[2];
#pragma unroll
    for (int i = 0; i < 2; i++) { ra[i] = *(const float4*)aptr[i]; rb[i] = *(const float4*)bptr[i]; }

    const int NSLAB = HDIM / 16;   // 32
    for (int s = 0; s < NSLAB; s++) {
        int cur = s & 1;
#pragma unroll
        for (int i = 0; i < 2; i++) {
            int kk = kq[i] * 4, r = rr[i];
            As[cur][kk+0][r] = f2tf32(ra[i].x); As[cur][kk+1][r] = f2tf32(ra[i].y);
            As[cur][kk+2][r] = f2tf32(ra[i].z); As[cur][kk+3][r] = f2tf32(ra[i].w);
            Bs[cur][kk+0][r] = f2tf32(rb[i].x); Bs[cur][kk+1][r] = f2tf32(rb[i].y);
            Bs[cur][kk+2][r] = f2tf32(rb[i].z); Bs[cur][kk+3][r] = f2tf32(rb[i].w);
        }
        __syncthreads();
        if (s + 1 < NSLAB) {
#pragma unroll
            for (int i = 0; i < 2; i++) {
                aptr[i] += 16; bptr[i] += 16;
                ra[i] = *(const float4*)aptr[i]; rb[i] = *(const float4*)bptr[i];
            }
        }
#pragma unroll
        for (int kk = 0; kk < 2; kk++) {   // two k8 steps
            uint32_t af[4][4], bf[4][2];
            const int kb = kk * 8;
#pragma unroll
            for (int mt = 0; mt < 4; mt++) {
                int mb = wm + mt * 16;
                af[mt][0] = As[cur][kb + cc    ][mb + g];
                af[mt][1] = As[cur][kb + cc    ][mb + g + 8];
                af[mt][2] = As[cur][kb + cc + 4][mb + g];
                af[mt][3] = As[cur][kb + cc + 4][mb + g + 8];
            }
#pragma unroll
            for (int nt = 0; nt < 4; nt++) {
                int nb = wn + nt * 8;
                bf[nt][0] = Bs[cur][kb + cc    ][nb + g];
                bf[nt][1] = Bs[cur][kb + cc + 4][nb + g];
            }
#pragma unroll
            for (int mt = 0; mt < 4; mt++)
#pragma unroll
                for (int nt = 0; nt < 4; nt++)
                    mma_tf32(acc[mt][nt], af[mt], bf[nt]);
        }
        __syncthreads();
    }

    // epilogue: bias + scatter store
#pragma unroll
    for (int mt = 0; mt < 4; mt++) {
#pragma unroll
        for (int h = 0; h < 2; h++) {
            int m = m0 + wm + mt * 16 + g + h * 8;
            if (m >= MDEC) continue;
            int bidx = m & 15;
            size_t crow = (size_t)(bidx * TDEC + (m >> 4)) * (size_t)VOC;
            const float* brow = bias + (size_t)bidx * (size_t)VOC;
#pragma unroll
            for (int nt = 0; nt < 4; nt++) {
                int n = n0 + wn + nt * 8 + 2 * cc;
                if (n < VOC) {
                    float v0 = acc[mt][nt][h*2+0] + brow[n];
                    float v1 = acc[mt][nt][h*2+1] + brow[n+1];
                    C[crow + n]     = v0;
                    C[crow + n + 1] = v1;
                }
            }
        }
    }
}

// encoder scan: 128 CTAs = 2 dirs x 64 slices of 8 h-dims, 384 threads
__global__ __launch_bounds__(384) void k_enc_scan(
    const float* __restrict__ Whh_f, const float* __restrict__ Whh_b,
    const float* __restrict__ bhh_f, const float* __restrict__ bhh_b)
{
    __shared__ float sH[16 * 516];
    __shared__ float sGh[24 * 16];
    __shared__ float sB[24];
    const int bx = blockIdx.x, dir = bx >> 6, jh0 = (bx & 63) * 8, tid = threadIdx.x;
    const float* Whh = dir ? Whh_b : Whh_f;
    const float* gi_base = dir ? g_gi_b : g_gi_f;
    if (tid < 24) sB[tid] = (dir ? bhh_b : bhh_f)[(tid >> 3) * HDIM + jh0 + (tid & 7)];

    const int jl = tid >> 4, bb = tid & 15;
    const float* wptr = Whh + (size_t)((jl >> 3) * HDIM + jh0 + (jl & 7)) * HDIM;

    for (int s = 0; s < SLEN; s++) {
        int par = s & 1;
        const float* hg = g_h_enc + (size_t)(dir * 2 + par) * BSZ * HDIM;
        for (int idx = tid * 4; idx < BSZ * HDIM; idx += 384 * 4) {
            int b = idx >> 9, k = idx & 511;
            *(float4*)(sH + b * 516 + k) = *(const float4*)(hg + b * HDIM + k);
        }
        __syncthreads();
        const float* hrow = sH + bb * 516;
        float a0=0.f,a1=0.f,a2=0.f,a3=0.f;
#pragma unroll 8
        for (int k = 0; k < HDIM; k += 4) {
            float4 w = __ldg((const float4*)(wptr + k));
            float4 h = *(const float4*)(hrow + k);
            a0 += w.x*h.x; a1 += w.y*h.y; a2 += w.z*h.z; a3 += w.w*h.w;
        }
        sGh[jl * 16 + bb] = (a0+a1)+(a2+a3) + sB[jl];
        __syncthreads();

        int s_x = dir ? (SLEN - 1 - s) : s;
        if (tid < 128) {
            int b = tid >> 3, lh = tid & 7;
            const float* gi = gi_base + (size_t)(s_x * BSZ + b) * H3 + jh0 + lh;
            float gir = gi[0], giz = gi[HDIM], gin = gi[2*HDIM];
            float ghr = sGh[lh*16+b], ghz = sGh[(8+lh)*16+b], ghn = sGh[(16+lh)*16+b];
            float hold = sH[b * 516 + jh0 + lh];
            float r = 1.f / (1.f + expf(-(gir + ghr)));
            float z = 1.f / (1.f + expf(-(giz + ghz)));
            float n = tanhf(gin + r * ghn);
            float hnew = (1.f - z) * n + z * hold;
            g_h_enc[((dir*2 + (par^1)) * BSZ + b) * HDIM + jh0 + lh] = hnew;
            g_enc_out[(size_t)(s_x * BSZ + b) * H2 + dir * HDIM + jh0 + lh] = hnew;
            if (s == SLEN - 1) g_hfinal[(dir * BSZ + b) * HDIM + jh0 + lh] = hnew;
        }
        grid_barrier(&g_bar[0], 128u * (unsigned)(s + 1));
    }
}

// decoder scan: 64 CTAs x slices of 8, 384 threads
__global__ __launch_bounds__(384) void k_dec_scan(
    const float* __restrict__ Whh, const float* __restrict__ bhh)
{
    __shared__ float sH[16 * 516];
    __shared__ float sGh[24 * 16];
    __shared__ float sB[24];
    const int jh0 = blockIdx.x * 8, tid = threadIdx.x;
    if (tid < 24) sB[tid] = bhh[(tid >> 3) * HDIM + jh0 + (tid & 7)];
    const int jl = tid >> 4, bb = tid & 15;
    const float* wptr = Whh + (size_t)((jl >> 3) * HDIM + jh0 + (jl & 7)) * HDIM;

    for (int t = 0; t < TDEC; t++) {
        int par = t & 1;
        const float* hg = g_hd + (size_t)par * BSZ * HDIM;
        for (int idx = tid * 4; idx < BSZ * HDIM; idx += 384 * 4) {
            int b = idx >> 9, k = idx & 511;
            *(float4*)(sH + b * 516 + k) = *(const float4*)(hg + b * HDIM + k);
        }
        __syncthreads();
        const float* hrow = sH + bb * 516;
        float a0=0.f,a1=0.f,a2=0.f,a3=0.f;
#pragma unroll 8
        for (int k = 0; k < HDIM; k += 4) {
            float4 w = __ldg((const float4*)(wptr + k));
            float4 h = *(const float4*)(hrow + k);
            a0 += w.x*h.x; a1 += w.y*h.y; a2 += w.z*h.z; a3 += w.w*h.w;
        }
        sGh[jl * 16 + bb] = (a0+a1)+(a2+a3) + sB[jl];
        __syncthreads();

        if (tid < 128) {
            int b = tid >> 3, lh = tid & 7;
            size_t gio = (size_t)(t * BSZ + b) * H3 + jh0 + lh;
            size_t cdo = (size_t)b * H3 + jh0 + lh;
            float gir = g_gidec[gio]          + g_cdec[cdo];
            float giz = g_gidec[gio + HDIM]   + g_cdec[cdo + HDIM];
            float gin = g_gidec[gio + 2*HDIM] + g_cdec[cdo + 2*HDIM];
            float ghr = sGh[lh*16+b], ghz = sGh[(8+lh)*16+b], ghn = sGh[(16+lh)*16+b];
            float hold = sH[b * 516 + jh0 + lh];
            float r = 1.f / (1.f + expf(-(gir + ghr)));
            float z = 1.f / (1.f + expf(-(giz + ghz)));
            float n = tanhf(gin + r * ghn);
            float hnew = (1.f - z) * n + z * hold;
            g_hd[((par^1) * BSZ + b) * HDIM + jh0 + lh] = hnew;
            g_hall[(size_t)(t * BSZ + b) * HDIM + jh0 + lh] = hnew;
        }
        grid_barrier(&g_bar[1], 64u * (unsigned)(t + 1));
    }
}

__global__ void k_v2h(const float* __restrict__ attn_W, const float* __restrict__ comb_W) {
    __shared__ float sc[HDIM];
    int tid = threadIdx.x;
    sc[tid] = comb_W[tid];
    __syncthreads();
    int c = blockIdx.x * 512 + tid;
    float acc = 0.f;
    for (int i = 0; i < HDIM; i++) acc += sc[i] * attn_W[(size_t)i * H3 + c];
    g_v[c] = acc;
}

__global__ __launch_bounds__(256) void k_attention(const int* __restrict__ mask) {
    __shared__ float sv[H2];
    __shared__ float sw[SLEN];
    __shared__ float red[SLEN];
    int b = blockIdx.x, tid = threadIdx.x;
    for (int i = tid; i < H2; i += 256) sv[i] = g_v[i];
    __syncthreads();
    float score = -1e30f;
    if (mask[b * SLEN + tid] > 0) {
        const float* e = g_enc_out + (size_t)(tid * BSZ + b) * H2;
        float a0=0.f,a1=0.f,a2=0.f,a3=0.f;
        for (int d = 0; d < H2; d += 4) {
            float4 ev = *(const float4*)(e + d);
            a0 += sv[d]*ev.x; a1 += sv[d+1]*ev.y; a2 += sv[d+2]*ev.z; a3 += sv[d+3]*ev.w;
        }
        score = (a0+a1)+(a2+a3);
    }
    red[tid] = score; __syncthreads();
    for (int o = 128; o; o >>= 1) { if (tid < o) red[tid] = fmaxf(red[tid], red[tid+o]); __syncthreads(); }
    float mx = red[0]; __syncthreads();
    float ex = (score > -1e29f) ? expf(score - mx) : 0.f;
    red[tid] = ex; __syncthreads();
    for (int o = 128; o; o >>= 1) { if (tid < o) red[tid] += red[tid+o]; __syncthreads(); }
    sw[tid] = ex / red[0];
    __syncthreads();
    float4 acc = make_float4(0.f,0.f,0.f,0.f);
    const float* base = g_enc_out + b * H2 + tid * 4;
    for (int s = 0; s < SLEN; s++) {
        float w = sw[s];
        float4 ev = *(const float4*)(base + (size_t)s * BSZ * H2);
        acc.x += w*ev.x; acc.y += w*ev.y; acc.z += w*ev.z; acc.w += w*ev.w;
    }
    *(float4*)(g_ctxraw + b * H2 + tid * 4) = acc;
}

__global__ void k_ctx_proj(const float* __restrict__ proj_W, const float* __restrict__ proj_b) {
    __shared__ float sc[H2];
    int b = blockIdx.x, j = threadIdx.x;
    for (int i = j; i < H2; i += 512) sc[i] = g_ctxraw[b * H2 + i];
    __syncthreads();
    const float* w = proj_W + (size_t)j * H2;
    float a0=0.f,a1=0.f,a2=0.f,a3=0.f;
    for (int d = 0; d < H2; d += 4) {
        float4 wv = *(const float4*)(w + d);
        a0 += sc[d]*wv.x; a1 += sc[d+1]*wv.y; a2 += sc[d+2]*wv.z; a3 += sc[d+3]*wv.w;
    }
    g_ctx[b * HDIM + j] = proj_b[j] + (a0+a1)+(a2+a3);
}

__global__ void k_cdec(const float* __restrict__ dec_Wih) {
    __shared__ float sc[HDIM];
    int b = blockIdx.x, tid = threadIdx.x;
    sc[tid] = g_ctx[b * HDIM + tid];
    __syncthreads();
    for (int r = 0; r < 3; r++) {
        int j3 = r * HDIM + tid;
        const float* w = dec_Wih + (size_t)j3 * (EDIM + HDIM) + EDIM;
        float a0=0.f,a1=0.f,a2=0.f,a3=0.f;
        for (int d = 0; d < HDIM; d += 4) {
            float4 wv = *(const float4*)(w + d);
            a0 += sc[d]*wv.x; a1 += sc[d+1]*wv.y; a2 += sc[d+2]*wv.z; a3 += sc[d+3]*wv.w;
        }
        g_cdec[b * H3 + j3] = (a0+a1)+(a2+a3);
    }
}

__global__ void k_hinit() {
    int b = blockIdx.x, k = threadIdx.x;
    g_hd[b * HDIM + k] = g_hfinal[b * HDIM + k] + g_hfinal[(BSZ + b) * HDIM + k];
}

__global__ __launch_bounds__(128) void k_ctxbias(const float* __restrict__ out_W,
                                                 const float* __restrict__ out_b) {
    __shared__ float sc[BSZ * HDIM];
    int tid = threadIdx.x;
    for (int i = tid; i < BSZ * HDIM; i += 128) sc[i] = g_ctx[i];
    __syncthreads();
    int v = blockIdx.x * 128 + tid;
    if (v >= VOC) return;
    float acc[BSZ];
#pragma unroll
    for (int b = 0; b < BSZ; b++) acc[b] = 0.f;
    const float* w = out_W + (size_t)v * H2 + HDIM;
    for (int d = 0; d < HDIM; d += 4) {
        float4 wv = *(const float4*)(w + d);
#pragma unroll
        for (int b = 0; b < BSZ; b++) {
            const float* cb = sc + b * HDIM + d;
            acc[b] += cb[0]*wv.x + cb[1]*wv.y + cb[2]*wv.z + cb[3]*wv.w;
        }
    }
    float ob = out_b[v];
#pragma unroll
    for (int b = 0; b < BSZ; b++) g_ctxbias[(size_t)b * VOC + v] = acc[b] + ob;
}

extern "C" void kernel_launch(void* const* d_in, const int* in_sizes, int n_in,
                              void* d_out, int out_size) {
    const float* bert    = (const float*)d_in[0];
    const int*   mask    = (const int*)  d_in[1];
    const int*   ids     = (const int*)  d_in[2];
    const float* emb     = (const float*)d_in[3];
    const float* eWih_f  = (const float*)d_in[4];
    const float* eWhh_f  = (const float*)d_in[5];
    const float* ebih_f  = (const float*)d_in[6];
    const float* ebhh_f  = (const float*)d_in[7];
    const float* eWih_b  = (const float*)d_in[8];
    const float* eWhh_b  = (const float*)d_in[9];
    const float* ebih_b  = (const float*)d_in[10];
    const float* ebhh_b  = (const float*)d_in[11];
    const float* dWih    = (const float*)d_in[12];
    const float* dWhh    = (const float*)d_in[13];
    const float* dbih    = (const float*)d_in[14];
    const float* dbhh    = (const float*)d_in[15];
    const float* attn_W  = (const float*)d_in[16];
    const float* proj_W  = (const float*)d_in[20];
    const float* proj_b  = (const float*)d_in[21];
    const float* out_W   = (const float*)d_in[22];
    const float* out_b   = (const float*)d_in[23];
    const float* comb_W  = (const float*)d_in[18];
    float* out = (float*)d_out;

    float *gi_f, *gi_b, *gidec, *hall, *ctxbias;
    cudaGetSymbolAddress((void**)&gi_f,   g_gi_f);
    cudaGetSymbolAddress((void**)&gi_b,   g_gi_b);
    cudaGetSymbolAddress((void**)&gidec,  g_gidec);
    cudaGetSymbolAddress((void**)&hall,   g_hall);
    cudaGetSymbolAddress((void**)&ctxbias,g_ctxbias);

    k_init<<<128, 256>>>(ids);

    // encoder input gates: [4096,768] x [1536,768]^T  (fp32, feeds recurrence)
    k_gemm<0><<<dim3(12, 32), 256>>>(bert, eWih_f, ebih_f, gi_f, SLEN*BSZ, H3, EDIM, EDIM, EDIM);
    k_gemm<0><<<dim3(12, 32), 256>>>(bert, eWih_b, ebih_b, gi_b, SLEN*BSZ, H3, EDIM, EDIM, EDIM);
    // decoder embedding gates (gathered rows)
    k_gemm<1><<<dim3(12, 13), 256>>>(emb, dWih, dbih, gidec, MDEC, H3, EDIM, EDIM, EDIM + HDIM);
    // v = comb_W @ attn_W[:, :2H]
    k_v2h<<<2, 512>>>(attn_W, comb_W);

    // encoder bidirectional scan (persistent, 128 CTAs)
    k_enc_scan<<<128, 384>>>(eWhh_f, eWhh_b, ebhh_f, ebhh_b);

    // step-invariant attention + context
    k_attention<<<BSZ, 256>>>(mask);
    k_ctx_proj<<<BSZ, 512>>>(proj_W, proj_b);
    k_cdec<<<BSZ, 512>>>(dWih);
    k_ctxbias<<<(VOC + 127) / 128, 128>>>(out_W, out_b);
    k_hinit<<<BSZ, 512>>>();

    // decoder scan (persistent, 64 CTAs)
    k_dec_scan<<<64, 384>>>(dWhh, dbhh);

    // logits via tf32 tensor cores: [1584,512] x [30522,1024(:512)]^T + ctxbias
    k_gemm_out_tf32<<<dim3(239, 13), 256>>>(hall, out_W, ctxbias, out);
}